// round 1
// baseline (speedup 1.0000x reference)
#include <cuda_runtime.h>

#define NB 2
#define NS 2048
#define ND 1024
#define NH 16
#define NHD 64

// Scratch: Q/K projections in [b, h, s, hd] layout, and E = exp(scores).
__device__ float g_Q[NB * NH * NS * NHD];          // 16.8 MB
__device__ float g_K[NB * NH * NS * NHD];          // 16.8 MB
__device__ float g_E[(size_t)NB * NH * NS * NS];   // 536 MB

// ---------------------------------------------------------------------------
// Projection GEMM: Out[b,h,s,hd] = (X[m,:] @ W^T + bias) * scale
// X: [4096, 1024], W: [1024, 1024] (row-major, torch Linear => out = X @ W^T)
// Tile: BM=128, BN=128, BK=16; 256 threads; 8x8 micro-tile per thread.
// ---------------------------------------------------------------------------
__global__ __launch_bounds__(256) void proj_kernel(
    const float* __restrict__ X, const float* __restrict__ W,
    const float* __restrict__ bias, float scale, int which)
{
    float* __restrict__ Out = which ? g_K : g_Q;

    __shared__ __align__(16) float As[128][16];   // [m][k]
    __shared__ __align__(16) float Bs[16][128];   // [k][n]  (Bs[k][n] = W[n][k])

    const int tid = threadIdx.x;
    const int tx = tid & 15;        // 16 col groups
    const int ty = tid >> 4;        // 16 row groups
    const int n0 = blockIdx.x * 128;
    const int m0 = blockIdx.y * 128;

    float acc[8][8];
#pragma unroll
    for (int i = 0; i < 8; i++)
#pragma unroll
        for (int j = 0; j < 8; j++) acc[i][j] = 0.0f;

    for (int kb = 0; kb < ND; kb += 16) {
        // Load A tile: 128 rows x 16 cols = 512 float4
#pragma unroll
        for (int t = 0; t < 2; t++) {
            int v = t * 256 + tid;
            int row = v >> 2, kq = v & 3;
            *(float4*)&As[row][kq * 4] =
                *(const float4*)&X[(m0 + row) * ND + kb + kq * 4];
        }
        // Load B tile transposed: Bs[k][n] = W[n0+n][kb+k]
#pragma unroll
        for (int t = 0; t < 2; t++) {
            int v = t * 256 + tid;
            int n = v >> 2, kq = v & 3;
            float4 f = *(const float4*)&W[(n0 + n) * ND + kb + kq * 4];
            Bs[kq * 4 + 0][n] = f.x;
            Bs[kq * 4 + 1][n] = f.y;
            Bs[kq * 4 + 2][n] = f.z;
            Bs[kq * 4 + 3][n] = f.w;
        }
        __syncthreads();

#pragma unroll
        for (int k4 = 0; k4 < 4; k4++) {
            float a[8][4];
#pragma unroll
            for (int i = 0; i < 8; i++) {
                float4 t4 = *(float4*)&As[ty * 8 + i][k4 * 4];
                a[i][0] = t4.x; a[i][1] = t4.y; a[i][2] = t4.z; a[i][3] = t4.w;
            }
#pragma unroll
            for (int u = 0; u < 4; u++) {
                int k = k4 * 4 + u;
                // cols: tx*4 .. +3 and 64+tx*4 .. +3 (stride-4 => conflict-free)
                float4 b0 = *(float4*)&Bs[k][tx * 4];
                float4 b1 = *(float4*)&Bs[k][64 + tx * 4];
                float bb[8] = {b0.x, b0.y, b0.z, b0.w, b1.x, b1.y, b1.z, b1.w};
#pragma unroll
                for (int i = 0; i < 8; i++)
#pragma unroll
                    for (int j = 0; j < 8; j++)
                        acc[i][j] += a[i][u] * bb[j];
            }
        }
        __syncthreads();
    }

    // Epilogue: add bias, scale, scatter to [b,h,s,hd]
#pragma unroll
    for (int i = 0; i < 8; i++) {
        int m = m0 + ty * 8 + i;
        int bb = m >> 11, s = m & 2047;
#pragma unroll
        for (int jh = 0; jh < 2; jh++) {
            int n = n0 + jh * 64 + tx * 4;
            int h = n >> 6, hd = n & 63;
            float4 o;
            o.x = (acc[i][jh * 4 + 0] + bias[n + 0]) * scale;
            o.y = (acc[i][jh * 4 + 1] + bias[n + 1]) * scale;
            o.z = (acc[i][jh * 4 + 2] + bias[n + 2]) * scale;
            o.w = (acc[i][jh * 4 + 3] + bias[n + 3]) * scale;
            *(float4*)&Out[((bb * NH + h) * NS + s) * NHD + hd] = o;
        }
    }
}

// ---------------------------------------------------------------------------
// Score kernel: for block (bh, q-tile of 64), loop over 32 k-tiles of 64.
// S = Qh[64,64] @ Kh[64,64]^T, then E = exp(S) stored to g_E.
// 256 threads, 4x4 micro-tile, dot-product along hd (kd-contiguous smem).
// No max subtraction: |scores| <= ~30 << log(FLT_MAX), fp32 exp is exact
// enough and softmax is shift-invariant.
// ---------------------------------------------------------------------------
__global__ __launch_bounds__(256) void score_kernel()
{
    __shared__ __align__(16) float Qs[64][68];   // [row][kd], pad 68 (2-way max)
    __shared__ __align__(16) float Ks[64][68];   // [col][kd]

    const int tid = threadIdx.x;
    const int tx = tid & 15;
    const int ty = tid >> 4;
    const int bh = blockIdx.x;              // b*16 + h
    const int q0 = blockIdx.y * 64;

    const float* __restrict__ Qp = g_Q + (bh * NS + q0) * NHD;
#pragma unroll
    for (int t = 0; t < 4; t++) {
        int v = t * 256 + tid;
        int row = v >> 4, hq = v & 15;
        *(float4*)&Qs[row][hq * 4] = *(const float4*)&Qp[row * NHD + hq * 4];
    }

    for (int kt = 0; kt < NS / 64; kt++) {
        const int k0 = kt * 64;
        const float* __restrict__ Kp = g_K + (bh * NS + k0) * NHD;

        __syncthreads();   // previous tile's compute done (also covers Q load)
#pragma unroll
        for (int t = 0; t < 4; t++) {
            int v = t * 256 + tid;
            int col = v >> 4, hq = v & 15;
            *(float4*)&Ks[col][hq * 4] = *(const float4*)&Kp[col * NHD + hq * 4];
        }
        __syncthreads();

        float acc[4][4];
#pragma unroll
        for (int i = 0; i < 4; i++)
#pragma unroll
            for (int j = 0; j < 4; j++) acc[i][j] = 0.0f;

#pragma unroll
        for (int k4 = 0; k4 < 16; k4++) {
            float4 a[4], bv[4];
#pragma unroll
            for (int i = 0; i < 4; i++)
                a[i] = *(float4*)&Qs[ty * 4 + i][k4 * 4];
#pragma unroll
            for (int j = 0; j < 4; j++)
                bv[j] = *(float4*)&Ks[tx * 4 + j][k4 * 4];
#pragma unroll
            for (int i = 0; i < 4; i++)
#pragma unroll
                for (int j = 0; j < 4; j++)
                    acc[i][j] += a[i].x * bv[j].x + a[i].y * bv[j].y +
                                 a[i].z * bv[j].z + a[i].w * bv[j].w;
        }

        // exp and store E tile
#pragma unroll
        for (int i = 0; i < 4; i++) {
            int row = q0 + ty * 4 + i;
            float4 e;
            e.x = __expf(acc[i][0]);
            e.y = __expf(acc[i][1]);
            e.z = __expf(acc[i][2]);
            e.w = __expf(acc[i][3]);
            *(float4*)&g_E[(size_t)(bh * NS + row) * NS + k0 + tx * 4] = e;
        }
    }
}

// ---------------------------------------------------------------------------
// Finalize: out[b,q,k] = (1/H) * sum_h E[b,h,q,k] / sum_k E[b,h,q,k]
// One block per (b,q) row; row kept in registers; block-reduce for l.
// ---------------------------------------------------------------------------
__global__ __launch_bounds__(256) void finalize_kernel(float* __restrict__ out)
{
    __shared__ float red[256];
    const int tid = threadIdx.x;
    const int bq = blockIdx.x;            // b*2048 + q
    const int b = bq >> 11, q = bq & 2047;

    float4 a0 = make_float4(0.f, 0.f, 0.f, 0.f);
    float4 a1 = a0;

    for (int h = 0; h < NH; h++) {
        const float* __restrict__ Ep =
            g_E + (size_t)((b * NH + h) * NS + q) * NS;
        float4 r0 = *(const float4*)&Ep[tid * 4];
        float4 r1 = *(const float4*)&Ep[(256 + tid) * 4];

        float ps = r0.x + r0.y + r0.z + r0.w + r1.x + r1.y + r1.z + r1.w;
        red[tid] = ps;
        __syncthreads();
#pragma unroll
        for (int s = 128; s > 0; s >>= 1) {
            if (tid < s) red[tid] += red[tid + s];
            __syncthreads();
        }
        float inv = 1.0f / red[0];
        __syncthreads();   // protect red[] before next h overwrites

        a0.x += r0.x * inv; a0.y += r0.y * inv;
        a0.z += r0.z * inv; a0.w += r0.w * inv;
        a1.x += r1.x * inv; a1.y += r1.y * inv;
        a1.z += r1.z * inv; a1.w += r1.w * inv;
    }

    const float sc = 1.0f / (float)NH;
    a0.x *= sc; a0.y *= sc; a0.z *= sc; a0.w *= sc;
    a1.x *= sc; a1.y *= sc; a1.z *= sc; a1.w *= sc;

    float* __restrict__ Op = out + (size_t)bq * NS;
    *(float4*)&Op[tid * 4] = a0;
    *(float4*)&Op[(256 + tid) * 4] = a1;
}

// ---------------------------------------------------------------------------
extern "C" void kernel_launch(void* const* d_in, const int* in_sizes, int n_in,
                              void* d_out, int out_size)
{
    const float* query = (const float*)d_in[0];
    const float* key   = (const float*)d_in[1];
    const float* Wq    = (const float*)d_in[2];
    const float* bq    = (const float*)d_in[3];
    const float* Wk    = (const float*)d_in[4];
    const float* bk    = (const float*)d_in[5];
    float* out = (float*)d_out;

    dim3 pg(ND / 128, (NB * NS) / 128);          // (8, 32)
    proj_kernel<<<pg, 256>>>(query, Wq, bq, 0.125f, 0);   // 1/sqrt(64)
    proj_kernel<<<pg, 256>>>(key,   Wk, bk, 1.0f,   1);
    score_kernel<<<dim3(NB * NH, NS / 64), 256>>>();      // (32, 32)
    finalize_kernel<<<NB * NS, 256>>>(out);               // 4096 blocks
}

// round 4
// speedup vs baseline: 2.2087x; 2.2087x over previous
#include <cuda_runtime.h>
#include <cuda_fp16.h>
#include <cstdint>

#define NB 2
#define NS 2048
#define ND 1024
#define NH 16
#define NHD 64

// Scratch
__device__ float  g_Q[NB * NH * NS * NHD];            // 16.8 MB fp32 [bh, s, hd]
__device__ float  g_K[NB * NH * NS * NHD];            // 16.8 MB fp32 [bh, s, hd]
__device__ __half g_E[(size_t)NB * NH * NS * NS];     // 268 MB fp16 exp(scores)
__device__ float  g_Linv[NB * NH * NS];               // 1/rowsum per (bh, q)

// ---------------------------------------------------------------------------
// fp32 -> tf32 (round to nearest) ; mma.sync tf32 (sm_80+, valid on sm_100)
// ---------------------------------------------------------------------------
__device__ __forceinline__ uint32_t f2tf(float f) {
    uint32_t u;
    asm("cvt.rna.tf32.f32 %0, %1;" : "=r"(u) : "f"(f));
    return u;
}

#define MMA_TF32(d, a, b0, b1)                                                 \
    asm volatile(                                                              \
        "mma.sync.aligned.m16n8k8.row.col.f32.tf32.tf32.f32 "                  \
        "{%0,%1,%2,%3}, {%4,%5,%6,%7}, {%8,%9}, {%0,%1,%2,%3};"                \
        : "+f"((d)[0]), "+f"((d)[1]), "+f"((d)[2]), "+f"((d)[3])               \
        : "r"((a)[0]), "r"((a)[1]), "r"((a)[2]), "r"((a)[3]),                  \
          "r"(b0), "r"(b1))

// ---------------------------------------------------------------------------
// Projection GEMM (SIMT): Out[b,h,s,hd] = (X @ W^T + bias) * scale
// ---------------------------------------------------------------------------
__global__ __launch_bounds__(256) void proj_kernel(
    const float* __restrict__ X, const float* __restrict__ W,
    const float* __restrict__ bias, float scale, int which)
{
    float* __restrict__ Out = which ? g_K : g_Q;

    __shared__ __align__(16) float As[128][16];
    __shared__ __align__(16) float Bs[16][128];

    const int tid = threadIdx.x;
    const int tx = tid & 15;
    const int ty = tid >> 4;
    const int n0 = blockIdx.x * 128;
    const int m0 = blockIdx.y * 128;

    float acc[8][8];
#pragma unroll
    for (int i = 0; i < 8; i++)
#pragma unroll
        for (int j = 0; j < 8; j++) acc[i][j] = 0.0f;

    for (int kb = 0; kb < ND; kb += 16) {
#pragma unroll
        for (int t = 0; t < 2; t++) {
            int v = t * 256 + tid;
            int row = v >> 2, kq = v & 3;
            *(float4*)&As[row][kq * 4] =
                *(const float4*)&X[(m0 + row) * ND + kb + kq * 4];
        }
#pragma unroll
        for (int t = 0; t < 2; t++) {
            int v = t * 256 + tid;
            int n = v >> 2, kq = v & 3;
            float4 f = *(const float4*)&W[(n0 + n) * ND + kb + kq * 4];
            Bs[kq * 4 + 0][n] = f.x;
            Bs[kq * 4 + 1][n] = f.y;
            Bs[kq * 4 + 2][n] = f.z;
            Bs[kq * 4 + 3][n] = f.w;
        }
        __syncthreads();

#pragma unroll
        for (int k4 = 0; k4 < 4; k4++) {
            float a[8][4];
#pragma unroll
            for (int i = 0; i < 8; i++) {
                float4 t4 = *(float4*)&As[ty * 8 + i][k4 * 4];
                a[i][0] = t4.x; a[i][1] = t4.y; a[i][2] = t4.z; a[i][3] = t4.w;
            }
#pragma unroll
            for (int u = 0; u < 4; u++) {
                int k = k4 * 4 + u;
                float4 b0 = *(float4*)&Bs[k][tx * 4];
                float4 b1 = *(float4*)&Bs[k][64 + tx * 4];
                float bb[8] = {b0.x, b0.y, b0.z, b0.w, b1.x, b1.y, b1.z, b1.w};
#pragma unroll
                for (int i = 0; i < 8; i++)
#pragma unroll
                    for (int j = 0; j < 8; j++)
                        acc[i][j] += a[i][u] * bb[j];
            }
        }
        __syncthreads();
    }

#pragma unroll
    for (int i = 0; i < 8; i++) {
        int m = m0 + ty * 8 + i;
        int bb = m >> 11, s = m & 2047;
#pragma unroll
        for (int jh = 0; jh < 2; jh++) {
            int n = n0 + jh * 64 + tx * 4;
            int h = n >> 6, hd = n & 63;
            float4 o;
            o.x = (acc[i][jh * 4 + 0] + bias[n + 0]) * scale;
            o.y = (acc[i][jh * 4 + 1] + bias[n + 1]) * scale;
            o.z = (acc[i][jh * 4 + 2] + bias[n + 2]) * scale;
            o.w = (acc[i][jh * 4 + 3] + bias[n + 3]) * scale;
            *(float4*)&Out[((bb * NH + h) * NS + s) * NHD + hd] = o;
        }
    }
}

// ---------------------------------------------------------------------------
// Score kernel (mma.sync tf32):
//   CTA = (head bh, q-tile of 128 rows). Loops 16 key tiles of 128.
//   8 warps; warp w owns rows [w*16, w*16+16) x all 128 cols.
//   A-fragments (Q) live in registers across the whole key loop.
//   Epilogue: exp -> fp16 g_E; running per-lane rowsums -> g_Linv.
// SMEM (dynamic): Qs[128][68] tf32, Ks[128][68] tf32  (stride 68 = no bank
// conflicts for B-fragment LDS: bank = 4*col + k%4, all distinct in a warp).
// ---------------------------------------------------------------------------
#define QS_STRIDE 68
#define SC_SMEM_TOTAL (2 * 128 * QS_STRIDE * 4)

__global__ __launch_bounds__(256) void score_kernel()
{
    extern __shared__ uint32_t smem[];
    uint32_t* Qs = smem;                     // [128][68]
    uint32_t* Ks = smem + 128 * QS_STRIDE;   // [128][68]

    const int tid = threadIdx.x;
    const int lane = tid & 31;
    const int wid = tid >> 5;
    const int lq = lane & 3;                 // threadID-in-group (k index)
    const int lg = lane >> 2;                // groupID (row/col index)
    const int bh = blockIdx.x;
    const int q0 = blockIdx.y * 128;

    // Stage Q tile -> tf32 smem
    const float* __restrict__ Qp = g_Q + ((size_t)bh * NS + q0) * NHD;
#pragma unroll
    for (int t = 0; t < 8; t++) {
        int v = t * 256 + tid;
        int r = v >> 4, c4 = v & 15;
        float4 f = *(const float4*)&Qp[r * NHD + c4 * 4];
        uint4 u = make_uint4(f2tf(f.x), f2tf(f.y), f2tf(f.z), f2tf(f.w));
        *(uint4*)&Qs[r * QS_STRIDE + c4 * 4] = u;
    }
    __syncthreads();

    // A fragments in registers: rows (wid*16 + lg) and +8, all 8 k-steps
    const int row_lo = wid * 16 + lg;
    uint32_t afr[8][4];
#pragma unroll
    for (int s = 0; s < 8; s++) {
        afr[s][0] = Qs[row_lo * QS_STRIDE + s * 8 + lq];
        afr[s][1] = Qs[(row_lo + 8) * QS_STRIDE + s * 8 + lq];
        afr[s][2] = Qs[row_lo * QS_STRIDE + s * 8 + lq + 4];
        afr[s][3] = Qs[(row_lo + 8) * QS_STRIDE + s * 8 + lq + 4];
    }

    float rs0 = 0.0f, rs1 = 0.0f;
    const size_t erow0 = ((size_t)bh * NS + q0 + row_lo) * NS;
    const size_t erow1 = ((size_t)bh * NS + q0 + row_lo + 8) * NS;

    for (int kt = 0; kt < NS / 128; kt++) {
        __syncthreads();   // all warps done reading previous Ks
        // Stage K tile -> tf32 smem
        const float* __restrict__ Kp = g_K + ((size_t)bh * NS + kt * 128) * NHD;
#pragma unroll
        for (int t = 0; t < 8; t++) {
            int v = t * 256 + tid;
            int r = v >> 4, c4 = v & 15;
            float4 f = *(const float4*)&Kp[r * NHD + c4 * 4];
            uint4 u = make_uint4(f2tf(f.x), f2tf(f.y), f2tf(f.z), f2tf(f.w));
            *(uint4*)&Ks[r * QS_STRIDE + c4 * 4] = u;
        }
        __syncthreads();

        float acc[16][4];
#pragma unroll
        for (int nt = 0; nt < 16; nt++)
#pragma unroll
            for (int j = 0; j < 4; j++) acc[nt][j] = 0.0f;

#pragma unroll
        for (int s = 0; s < 8; s++) {
#pragma unroll
            for (int nt = 0; nt < 16; nt++) {
                const int col = nt * 8 + lg;
                uint32_t b0 = Ks[col * QS_STRIDE + s * 8 + lq];
                uint32_t b1 = Ks[col * QS_STRIDE + s * 8 + lq + 4];
                MMA_TF32(acc[nt], afr[s], b0, b1);
            }
        }

        // Epilogue: exp -> fp16 store, accumulate rowsums
#pragma unroll
        for (int nt = 0; nt < 16; nt++) {
            float e0 = __expf(acc[nt][0]);
            float e1 = __expf(acc[nt][1]);
            float e2 = __expf(acc[nt][2]);
            float e3 = __expf(acc[nt][3]);
            rs0 += e0 + e1;
            rs1 += e2 + e3;
            const int col = kt * 128 + nt * 8 + 2 * lq;
            *(__half2*)&g_E[erow0 + col] = __floats2half2_rn(e0, e1);
            *(__half2*)&g_E[erow1 + col] = __floats2half2_rn(e2, e3);
        }
    }

    // Reduce rowsums across the 4 lanes of each group (lq = 0..3)
    rs0 += __shfl_xor_sync(0xFFFFFFFF, rs0, 1);
    rs0 += __shfl_xor_sync(0xFFFFFFFF, rs0, 2);
    rs1 += __shfl_xor_sync(0xFFFFFFFF, rs1, 1);
    rs1 += __shfl_xor_sync(0xFFFFFFFF, rs1, 2);
    if (lq == 0) {
        g_Linv[bh * NS + q0 + row_lo] = 1.0f / rs0;
        g_Linv[bh * NS + q0 + row_lo + 8] = 1.0f / rs1;
    }
}

// ---------------------------------------------------------------------------
// Finalize: out[b,q,k] = sum_h E[b,h,q,k] * Linv[b,h,q] / H   (pure streaming)
// ---------------------------------------------------------------------------
__global__ __launch_bounds__(256) void finalize_kernel(float* __restrict__ out)
{
    const int tid = threadIdx.x;
    const int bq = blockIdx.x;
    const int b = bq >> 11, q = bq & 2047;

    float acc[8];
#pragma unroll
    for (int j = 0; j < 8; j++) acc[j] = 0.0f;

    for (int h = 0; h < NH; h++) {
        const int bhh = b * NH + h;
        const float w = g_Linv[(bhh << 11) + q] * (1.0f / (float)NH);
        const uint4* __restrict__ Ep =
            (const uint4*)(g_E + ((size_t)bhh * NS + q) * NS) + tid;
        uint4 v = *Ep;
        const __half2* hp = (const __half2*)&v;
#pragma unroll
        for (int j = 0; j < 4; j++) {
            float2 f = __half22float2(hp[j]);
            acc[2 * j] += f.x * w;
            acc[2 * j + 1] += f.y * w;
        }
    }

    float4* __restrict__ Op = (float4*)(out + (size_t)bq * NS);
    Op[tid * 2 + 0] = make_float4(acc[0], acc[1], acc[2], acc[3]);
    Op[tid * 2 + 1] = make_float4(acc[4], acc[5], acc[6], acc[7]);
}

// ---------------------------------------------------------------------------
extern "C" void kernel_launch(void* const* d_in, const int* in_sizes, int n_in,
                              void* d_out, int out_size)
{
    const float* query = (const float*)d_in[0];
    const float* key   = (const float*)d_in[1];
    const float* Wq    = (const float*)d_in[2];
    const float* bq    = (const float*)d_in[3];
    const float* Wk    = (const float*)d_in[4];
    const float* bk    = (const float*)d_in[5];
    float* out = (float*)d_out;

    cudaFuncSetAttribute(score_kernel,
                         cudaFuncAttributeMaxDynamicSharedMemorySize,
                         SC_SMEM_TOTAL);

    dim3 pg(ND / 128, (NB * NS) / 128);
    proj_kernel<<<pg, 256>>>(query, Wq, bq, 0.125f, 0);   // 1/sqrt(64)
    proj_kernel<<<pg, 256>>>(key,   Wk, bk, 1.0f,   1);
    score_kernel<<<dim3(NB * NH, NS / 128), 256, SC_SMEM_TOTAL>>>();
    finalize_kernel<<<NB * NS, 256>>>(out);
}

// round 5
// speedup vs baseline: 3.5277x; 1.5972x over previous
#include <cuda_runtime.h>
#include <cuda_fp16.h>
#include <cstdint>

#define NB 2
#define NS 2048
#define ND 1024
#define NH 16
#define NHD 64

// Scratch
__device__ float  g_Q[NB * NH * NS * NHD];            // fp32 [bh, s, hd]
__device__ float  g_K[NB * NH * NS * NHD];            // fp32 [bh, s, hd]
__device__ __half g_E[(size_t)NB * NH * NS * NS];     // 268 MB fp16 exp(scores)
__device__ float  g_Linv[NB * NH * NS];               // 1/rowsum per (bh, q)

// ---------------------------------------------------------------------------
__device__ __forceinline__ uint32_t f2tf(float f) {
    uint32_t u;
    asm("cvt.rna.tf32.f32 %0, %1;" : "=r"(u) : "f"(f));
    return u;
}
__device__ __forceinline__ uint32_t smem_u32(const void* p) {
    uint32_t a;
    asm("{ .reg .u64 t; cvta.to.shared.u64 t, %1; cvt.u32.u64 %0, t; }"
        : "=r"(a) : "l"(p));
    return a;
}
__device__ __forceinline__ void cp16(uint32_t s, const void* g) {
    asm volatile("cp.async.cg.shared.global [%0], [%1], 16;"
                 :: "r"(s), "l"(g));
}
#define CP_COMMIT() asm volatile("cp.async.commit_group;" ::: "memory")
#define CP_WAIT1()  asm volatile("cp.async.wait_group 1;" ::: "memory")

#define MMA_TF32(d, a, b0, b1)                                                 \
    asm volatile(                                                              \
        "mma.sync.aligned.m16n8k8.row.col.f32.tf32.tf32.f32 "                  \
        "{%0,%1,%2,%3}, {%4,%5,%6,%7}, {%8,%9}, {%0,%1,%2,%3};"                \
        : "+f"((d)[0]), "+f"((d)[1]), "+f"((d)[2]), "+f"((d)[3])               \
        : "r"((a)[0]), "r"((a)[1]), "r"((a)[2]), "r"((a)[3]),                  \
          "r"(b0), "r"(b1))

// ---------------------------------------------------------------------------
// Projection GEMM on mma.sync tf32:
//   Out[b,h,s,hd] = (X @ W^T + bias) * scale
//   BM=128, BN=128, BK=32, double-buffered cp.async. 8 warps, warp = 16x128.
//   smem stride 36 floats (144B: 16B-aligned chunks, conflict-free frags).
// ---------------------------------------------------------------------------
#define PJ_STRIDE 36
#define PJ_BUF (128 * PJ_STRIDE)                       // floats per buffer
#define PJ_SMEM_TOTAL (4 * PJ_BUF * 4)                 // X[2] + W[2], bytes

__global__ __launch_bounds__(256) void proj_mma_kernel(
    const float* __restrict__ X, const float* __restrict__ W,
    const float* __restrict__ bias, float scale, int which)
{
    float* __restrict__ Out = which ? g_K : g_Q;
    extern __shared__ float pjs[];
    float* Xs = pjs;                  // [2][128][36]
    float* Ws = pjs + 2 * PJ_BUF;     // [2][128][36]
    const uint32_t sb_x = smem_u32(Xs);
    const uint32_t sb_w = smem_u32(Ws);

    const int tid = threadIdx.x;
    const int lane = tid & 31, wid = tid >> 5;
    const int lq = lane & 3, lg = lane >> 2;
    const int n0 = blockIdx.x * 128, m0 = blockIdx.y * 128;
    const int row_lo = wid * 16 + lg;

    // async-stage one BK=32 slab of X and W into buffer st
    const int ld_row = tid >> 1;              // 128 rows, 2 threads/row
    const int ld_c0 = (tid & 1) * 16;         // float col base (16 floats each)
    auto prefetch = [&](int st, int kb) {
        uint32_t xs = sb_x + (uint32_t)((st * PJ_BUF + ld_row * PJ_STRIDE + ld_c0) * 4);
        uint32_t ws = sb_w + (uint32_t)((st * PJ_BUF + ld_row * PJ_STRIDE + ld_c0) * 4);
        const float* xg = X + (size_t)(m0 + ld_row) * ND + kb + ld_c0;
        const float* wg = W + (size_t)(n0 + ld_row) * ND + kb + ld_c0;
#pragma unroll
        for (int i = 0; i < 4; i++) {
            cp16(xs + i * 16, xg + i * 4);
            cp16(ws + i * 16, wg + i * 4);
        }
    };

    float acc[16][4];
#pragma unroll
    for (int nt = 0; nt < 16; nt++)
#pragma unroll
        for (int j = 0; j < 4; j++) acc[nt][j] = 0.0f;

    prefetch(0, 0);
    CP_COMMIT();

    for (int kb_i = 0; kb_i < ND / 32; kb_i++) {
        if (kb_i + 1 < ND / 32) prefetch((kb_i + 1) & 1, (kb_i + 1) * 32);
        CP_COMMIT();
        CP_WAIT1();
        __syncthreads();

        const float* Xb = Xs + (kb_i & 1) * PJ_BUF;
        const float* Wb = Ws + (kb_i & 1) * PJ_BUF;
#pragma unroll
        for (int s = 0; s < 4; s++) {
            uint32_t a[4];
            a[0] = __float_as_uint(Xb[row_lo * PJ_STRIDE + s * 8 + lq]);
            a[1] = __float_as_uint(Xb[(row_lo + 8) * PJ_STRIDE + s * 8 + lq]);
            a[2] = __float_as_uint(Xb[row_lo * PJ_STRIDE + s * 8 + lq + 4]);
            a[3] = __float_as_uint(Xb[(row_lo + 8) * PJ_STRIDE + s * 8 + lq + 4]);
#pragma unroll
            for (int nt = 0; nt < 16; nt++) {
                uint32_t b0 = __float_as_uint(Wb[(nt * 8 + lg) * PJ_STRIDE + s * 8 + lq]);
                uint32_t b1 = __float_as_uint(Wb[(nt * 8 + lg) * PJ_STRIDE + s * 8 + lq + 4]);
                MMA_TF32(acc[nt], a, b0, b1);
            }
        }
        __syncthreads();
    }

    // Epilogue: bias + scale, scatter to [bh, s, hd]; 32B-sector-aligned stores
    const int m_lo = m0 + row_lo;
    const int b_lo = m_lo >> 11, s_lo = m_lo & 2047;
    const int m_hi = m_lo + 8;
    const int b_hi = m_hi >> 11, s_hi = m_hi & 2047;
#pragma unroll
    for (int nt = 0; nt < 16; nt++) {
        int n = n0 + nt * 8 + 2 * lq;
        float2 bb = *(const float2*)&bias[n];
        int h = n >> 6, hd = n & 63;
        float2 o0, o1;
        o0.x = (acc[nt][0] + bb.x) * scale;
        o0.y = (acc[nt][1] + bb.y) * scale;
        o1.x = (acc[nt][2] + bb.x) * scale;
        o1.y = (acc[nt][3] + bb.y) * scale;
        *(float2*)&Out[((size_t)(b_lo * NH + h) * NS + s_lo) * NHD + hd] = o0;
        *(float2*)&Out[((size_t)(b_hi * NH + h) * NS + s_hi) * NHD + hd] = o1;
    }
}

// ---------------------------------------------------------------------------
// Score kernel (mma.sync tf32, double-buffered K, staged E stores):
//   CTA = (head bh, q-tile 128). 16 key tiles of 128. 8 warps, warp = 16x128.
// SMEM: Qs[128][68] tf32 | Ks[2][128][68] fp32 (cp.async) | stg[8][16][136] half
// ---------------------------------------------------------------------------
#define QS_STRIDE 68
#define KS_OFF    (128 * QS_STRIDE * 4)                   // 34816 B
#define STG_OFF   (KS_OFF + 2 * 128 * QS_STRIDE * 4)      // 104448 B
#define STG_ROW   136
#define SC_SMEM_TOTAL (STG_OFF + 8 * 16 * STG_ROW * 2)    // 139264 B

__global__ __launch_bounds__(256) void score_kernel()
{
    extern __shared__ char smem[];
    uint32_t* Qs = (uint32_t*)smem;                 // [128][68] tf32
    float* Ks = (float*)(smem + KS_OFF);            // [2][128][68]
    const uint32_t sb_k = smem_u32(Ks);

    const int tid = threadIdx.x;
    const int lane = tid & 31;
    const int wid = tid >> 5;
    const int lq = lane & 3;
    const int lg = lane >> 2;
    const int bh = blockIdx.x;
    const int q0 = blockIdx.y * 128;

    __half* stg = (__half*)(smem + STG_OFF) + wid * 16 * STG_ROW;

    // K prefetch: 128 rows x 64 floats; 2 threads/row, 8 chunks each
    const int kl_row = tid >> 1;
    const int kl_c0 = (tid & 1) * 32;          // float col base
    auto prefetch = [&](int st, int kt) {
        uint32_t ks = sb_k + (uint32_t)((st * 128 * QS_STRIDE + kl_row * QS_STRIDE + kl_c0) * 4);
        const float* kg = g_K + ((size_t)bh * NS + kt * 128 + kl_row) * NHD + kl_c0;
#pragma unroll
        for (int i = 0; i < 8; i++) cp16(ks + i * 16, kg + i * 4);
    };

    prefetch(0, 0);
    CP_COMMIT();

    // Stage Q tile -> tf32 smem (rounded)
    const float* __restrict__ Qp = g_Q + ((size_t)bh * NS + q0) * NHD;
#pragma unroll
    for (int t = 0; t < 8; t++) {
        int v = t * 256 + tid;
        int r = v >> 4, c4 = v & 15;
        float4 f = *(const float4*)&Qp[r * NHD + c4 * 4];
        uint4 u = make_uint4(f2tf(f.x), f2tf(f.y), f2tf(f.z), f2tf(f.w));
        *(uint4*)&Qs[r * QS_STRIDE + c4 * 4] = u;
    }
    __syncthreads();

    const int row_lo = wid * 16 + lg;
    uint32_t afr[8][4];
#pragma unroll
    for (int s = 0; s < 8; s++) {
        afr[s][0] = Qs[row_lo * QS_STRIDE + s * 8 + lq];
        afr[s][1] = Qs[(row_lo + 8) * QS_STRIDE + s * 8 + lq];
        afr[s][2] = Qs[row_lo * QS_STRIDE + s * 8 + lq + 4];
        afr[s][3] = Qs[(row_lo + 8) * QS_STRIDE + s * 8 + lq + 4];
    }

    float rs0 = 0.0f, rs1 = 0.0f;

    for (int kt = 0; kt < NS / 128; kt++) {
        if (kt + 1 < NS / 128) prefetch((kt + 1) & 1, kt + 1);
        CP_COMMIT();
        CP_WAIT1();
        __syncthreads();

        const float* Kb = Ks + (kt & 1) * 128 * QS_STRIDE;

        float acc[16][4];
#pragma unroll
        for (int nt = 0; nt < 16; nt++)
#pragma unroll
            for (int j = 0; j < 4; j++) acc[nt][j] = 0.0f;

#pragma unroll
        for (int s = 0; s < 8; s++) {
#pragma unroll
            for (int nt = 0; nt < 16; nt++) {
                const int col = nt * 8 + lg;
                uint32_t b0 = __float_as_uint(Kb[col * QS_STRIDE + s * 8 + lq]);
                uint32_t b1 = __float_as_uint(Kb[col * QS_STRIDE + s * 8 + lq + 4]);
                MMA_TF32(acc[nt], afr[s], b0, b1);
            }
        }

        // Epilogue: exp -> fp16, stage in smem, coalesced row stores
#pragma unroll
        for (int nt = 0; nt < 16; nt++) {
            float e0 = __expf(acc[nt][0]);
            float e1 = __expf(acc[nt][1]);
            float e2 = __expf(acc[nt][2]);
            float e3 = __expf(acc[nt][3]);
            rs0 += e0 + e1;
            rs1 += e2 + e3;
            *(__half2*)&stg[lg * STG_ROW + nt * 8 + 2 * lq] = __floats2half2_rn(e0, e1);
            *(__half2*)&stg[(lg + 8) * STG_ROW + nt * 8 + 2 * lq] = __floats2half2_rn(e2, e3);
        }
        __syncwarp();
#pragma unroll
        for (int r = 0; r < 16; r++) {
            uint2 v = *(uint2*)&stg[r * STG_ROW + lane * 4];
            *(uint2*)&g_E[((size_t)bh * NS + q0 + wid * 16 + r) * NS + kt * 128 + lane * 4] = v;
        }
        __syncwarp();
        __syncthreads();   // done reading Ks[kt&1] before prefetch kt+2 lands
    }

    // Reduce rowsums across the 4 lanes of each group
    rs0 += __shfl_xor_sync(0xFFFFFFFF, rs0, 1);
    rs0 += __shfl_xor_sync(0xFFFFFFFF, rs0, 2);
    rs1 += __shfl_xor_sync(0xFFFFFFFF, rs1, 1);
    rs1 += __shfl_xor_sync(0xFFFFFFFF, rs1, 2);
    if (lq == 0) {
        g_Linv[bh * NS + q0 + row_lo] = 1.0f / rs0;
        g_Linv[bh * NS + q0 + row_lo + 8] = 1.0f / rs1;
    }
}

// ---------------------------------------------------------------------------
// Finalize: out[b,q,k] = sum_h E[b,h,q,k] * Linv[b,h,q] / H   (pure streaming)
// ---------------------------------------------------------------------------
__global__ __launch_bounds__(256) void finalize_kernel(float* __restrict__ out)
{
    const int tid = threadIdx.x;
    const int bq = blockIdx.x;
    const int b = bq >> 11, q = bq & 2047;

    float acc[8];
#pragma unroll
    for (int j = 0; j < 8; j++) acc[j] = 0.0f;

    for (int h = 0; h < NH; h++) {
        const int bhh = b * NH + h;
        const float w = g_Linv[(bhh << 11) + q] * (1.0f / (float)NH);
        const uint4* __restrict__ Ep =
            (const uint4*)(g_E + ((size_t)bhh * NS + q) * NS) + tid;
        uint4 v = *Ep;
        const __half2* hp = (const __half2*)&v;
#pragma unroll
        for (int j = 0; j < 4; j++) {
            float2 f = __half22float2(hp[j]);
            acc[2 * j] += f.x * w;
            acc[2 * j + 1] += f.y * w;
        }
    }

    float4* __restrict__ Op = (float4*)(out + (size_t)bq * NS);
    Op[tid * 2 + 0] = make_float4(acc[0], acc[1], acc[2], acc[3]);
    Op[tid * 2 + 1] = make_float4(acc[4], acc[5], acc[6], acc[7]);
}

// ---------------------------------------------------------------------------
extern "C" void kernel_launch(void* const* d_in, const int* in_sizes, int n_in,
                              void* d_out, int out_size)
{
    const float* query = (const float*)d_in[0];
    const float* key   = (const float*)d_in[1];
    const float* Wq    = (const float*)d_in[2];
    const float* bq    = (const float*)d_in[3];
    const float* Wk    = (const float*)d_in[4];
    const float* bk    = (const float*)d_in[5];
    float* out = (float*)d_out;

    cudaFuncSetAttribute(proj_mma_kernel,
                         cudaFuncAttributeMaxDynamicSharedMemorySize,
                         PJ_SMEM_TOTAL);
    cudaFuncSetAttribute(score_kernel,
                         cudaFuncAttributeMaxDynamicSharedMemorySize,
                         SC_SMEM_TOTAL);

    dim3 pg(ND / 128, (NB * NS) / 128);   // (8, 32)
    proj_mma_kernel<<<pg, 256, PJ_SMEM_TOTAL>>>(query, Wq, bq, 0.125f, 0);
    proj_mma_kernel<<<pg, 256, PJ_SMEM_TOTAL>>>(key,   Wk, bk, 1.0f,   1);
    score_kernel<<<dim3(NB * NH, NS / 128), 256, SC_SMEM_TOTAL>>>();
    finalize_kernel<<<NB * NS, 256>>>(out);
}